// round 1
// baseline (speedup 1.0000x reference)
#include <cuda_runtime.h>
#include <cuda_bf16.h>

#define NN 8192
#define BB 4096
#define EPSV 1e-7f

// Flattened ancestor chain per node: {a1, a2, a3, parent_clip}
// Missing ancestors / root-parent point at sentinel index NN (value 1.0 in smem).
__device__ int4  g_anc[NN];
__device__ float g_partial[BB];

__global__ void anc_setup_kernel(const int* __restrict__ parent, int n) {
    int c = blockIdx.x * blockDim.x + threadIdx.x;
    if (c < n) {
        int a1 = parent[c];
        int a2 = (a1 >= 0) ? parent[a1] : -1;
        int a3 = (a2 >= 0) ? parent[a2] : -1;
        int4 v;
        v.x = (a1 >= 0) ? a1 : n;
        v.y = (a2 >= 0) ? a2 : n;
        v.z = (a3 >= 0) ? a3 : n;
        v.w = (a1 >= 0) ? a1 : n;   // parent_clip for mask gather
        g_anc[c] = v;
    }
}

__device__ __forceinline__ float fsigmoid(float x) {
    return __fdividef(1.0f, 1.0f + __expf(-x));
}

// One CTA per row. Dynamic smem: sp[8196] (sigmoid of row, padded), st[8193+] (target row).
__global__ __launch_bounds__(256, 3)
void cond_sigmoid_row_kernel(const float* __restrict__ pred,
                             const float* __restrict__ target,
                             float* __restrict__ out_clone) {
    extern __shared__ float smem[];
    float* sp = smem;            // [8196] (8192 data + sentinel + pad)
    float* st = smem + 8196;     // [8196]

    const int b   = blockIdx.x;
    const int tid = threadIdx.x;
    const size_t row = (size_t)b * NN;

    // Phase 1: stream row, compute sigmoid into smem, stage target row.
    const float4* pr = (const float4*)(pred   + row);
    const float4* tg = (const float4*)(target + row);
    #pragma unroll
    for (int i = tid; i < NN / 4; i += 256) {
        float4 v = pr[i];
        float4 s;
        s.x = fsigmoid(v.x); s.y = fsigmoid(v.y);
        s.z = fsigmoid(v.z); s.w = fsigmoid(v.w);
        ((float4*)sp)[i] = s;
        ((float4*)st)[i] = tg[i];
    }
    if (tid == 0) { sp[NN] = 1.0f; st[NN] = 1.0f; }
    __syncthreads();

    // Phase 2: conditional-prob chain product + masked BCE accumulation.
    float acc = 0.0f;
    float* oc = out_clone + row;
    #pragma unroll 4
    for (int c = tid; c < NN; c += 256) {
        int4 a  = g_anc[c];
        float p = sp[c];
        float pc = p * sp[a.x] * sp[a.y] * sp[a.z];
        oc[c] = pc;

        float t = st[c];
        float m = st[a.w];                       // 1.0 for roots via sentinel
        float pcl  = fminf(fmaxf(p, EPSV), 1.0f - EPSV);
        float coef = (t > 0.0f) ? 1.0f : m;      // targets are {0,1}
        float arg  = (t > 0.0f) ? pcl  : 1.0f - pcl;
        acc += coef * __logf(arg);               // negative; negate at the end
    }

    // Block reduction (8 warps).
    #pragma unroll
    for (int o = 16; o > 0; o >>= 1)
        acc += __shfl_xor_sync(0xFFFFFFFFu, acc, o);
    __shared__ float red[8];
    if ((tid & 31) == 0) red[tid >> 5] = acc;
    __syncthreads();
    if (tid < 8) {
        float v = red[tid];
        #pragma unroll
        for (int o = 4; o > 0; o >>= 1)
            v += __shfl_xor_sync(0xFFu, v, o);
        if (tid == 0) g_partial[b] = v;
    }
}

__global__ void final_reduce_kernel(float* __restrict__ out, int nrows) {
    __shared__ double sred[32];
    int tid = threadIdx.x;
    double s = 0.0;
    for (int i = tid; i < nrows; i += 1024) s += (double)g_partial[i];
    #pragma unroll
    for (int o = 16; o > 0; o >>= 1)
        s += __shfl_xor_sync(0xFFFFFFFFu, s, o);
    if ((tid & 31) == 0) sred[tid >> 5] = s;
    __syncthreads();
    if (tid < 32) {
        double v = sred[tid];
        #pragma unroll
        for (int o = 16; o > 0; o >>= 1)
            v += __shfl_xor_sync(0xFFFFFFFFu, v, o);
        if (tid == 0) out[0] = (float)(-v / (double)nrows);
    }
}

extern "C" void kernel_launch(void* const* d_in, const int* in_sizes, int n_in,
                              void* d_out, int out_size) {
    const float* pred   = (const float*)d_in[0];
    const float* target = (const float*)d_in[1];
    const int*   parent = (const int*)d_in[2];
    // d_in[3] = level_of (encoded in ancestor chain), d_in[4] = mode (always EVAL here)

    const int N = in_sizes[2];                 // 8192
    const int B = in_sizes[0] / N;             // 4096

    float* out       = (float*)d_out;          // out[0] = loss
    float* out_clone = out + 1;                // out[1..] = pred_clone [B,N]

    static const size_t SMEM_BYTES = (8196 + 8196) * sizeof(float);
    cudaFuncSetAttribute(cond_sigmoid_row_kernel,
                         cudaFuncAttributeMaxDynamicSharedMemorySize,
                         (int)SMEM_BYTES);

    anc_setup_kernel<<<(N + 255) / 256, 256>>>(parent, N);
    cond_sigmoid_row_kernel<<<B, 256, SMEM_BYTES>>>(pred, target, out_clone);
    final_reduce_kernel<<<1, 1024>>>(out, B);
}

// round 2
// speedup vs baseline: 1.1324x; 1.1324x over previous
#include <cuda_runtime.h>
#include <cuda_bf16.h>

#define NN 8192
#define BB 4096
#define EPSV 1e-7f
// Levels 0..2 = 8 + 128 + 2048 = 2184. Every ancestor (parent of any node) is < 2184.
#define ANC_SENT 2184
#define TBL 2192   // padded table size

// Packed ancestor chain per node: {a1, a2, a3, pad}, sentinel = ANC_SENT (smem value 1.0).
// a.w unused (mask gather index == a1). 8 B/node -> 64 KB table, L1-resident.
__device__ ushort4 g_anc[NN];
__device__ float   g_partial[BB];

__global__ void anc_setup_kernel(const int* __restrict__ parent, int n) {
    int c = blockIdx.x * blockDim.x + threadIdx.x;
    if (c < n) {
        int a1 = parent[c];
        int a2 = (a1 >= 0) ? parent[a1] : -1;
        int a3 = (a2 >= 0) ? parent[a2] : -1;
        ushort4 v;
        v.x = (unsigned short)((a1 >= 0) ? a1 : ANC_SENT);
        v.y = (unsigned short)((a2 >= 0) ? a2 : ANC_SENT);
        v.z = (unsigned short)((a3 >= 0) ? a3 : ANC_SENT);
        v.w = 0;
        g_anc[c] = v;
    }
}

__device__ __forceinline__ float fsigmoid(float x) {
    return __fdividef(1.0f, 1.0f + __expf(-x));
}

// One CTA per row. Static smem: sigmoid table + target table for indices [0, 2184].
__global__ __launch_bounds__(256, 8)
void cond_sigmoid_row_kernel(const float* __restrict__ pred,
                             const float* __restrict__ target,
                             float* __restrict__ out_clone) {
    __shared__ float sp[TBL];   // sigmoid(pred[b, 0..2183]) + sentinel 1.0
    __shared__ float st[TBL];   // target[b, 0..2183]        + sentinel 1.0

    const int b   = blockIdx.x;
    const int tid = threadIdx.x;
    const size_t row = (size_t)b * NN;

    const float4* pr = (const float4*)(pred   + row);
    const float4* tg = (const float4*)(target + row);

    // Phase 1: stage ancestor tables (first 2184 elements; 2184/4 = 546 float4s).
    for (int i = tid; i < ANC_SENT / 4; i += 256) {
        float4 v = pr[i];
        float4 s;
        s.x = fsigmoid(v.x); s.y = fsigmoid(v.y);
        s.z = fsigmoid(v.z); s.w = fsigmoid(v.w);
        ((float4*)sp)[i] = s;
        ((float4*)st)[i] = tg[i];
    }
    if (tid == 0) { sp[ANC_SENT] = 1.0f; st[ANC_SENT] = 1.0f; }
    __syncthreads();

    // Phase 2: single streaming pass over the full row.
    float acc = 0.0f;
    float* oc = out_clone + row;
    const uint4* anc4 = (const uint4*)g_anc;   // 2 ushort4 entries per uint4

    #pragma unroll 2
    for (int i = tid; i < NN / 4; i += 256) {
        float4 pv = pr[i];
        float4 tv = tg[i];
        // ancestor entries for elements 4i..4i+3: 32 contiguous bytes
        uint4 e0 = anc4[2 * i];
        uint4 e1 = anc4[2 * i + 1];

        float p0 = fsigmoid(pv.x), p1 = fsigmoid(pv.y);
        float p2 = fsigmoid(pv.z), p3 = fsigmoid(pv.w);

        int a10 = e0.x & 0xFFFF, a20 = e0.x >> 16, a30 = e0.y & 0xFFFF;
        int a11 = e0.z & 0xFFFF, a21 = e0.z >> 16, a31 = e0.w & 0xFFFF;
        int a12 = e1.x & 0xFFFF, a22 = e1.x >> 16, a32 = e1.y & 0xFFFF;
        int a13 = e1.z & 0xFFFF, a23 = e1.z >> 16, a33 = e1.w & 0xFFFF;

        float c0 = p0 * sp[a10] * sp[a20] * sp[a30];
        float c1 = p1 * sp[a11] * sp[a21] * sp[a31];
        float c2 = p2 * sp[a12] * sp[a22] * sp[a32];
        float c3 = p3 * sp[a13] * sp[a23] * sp[a33];

        int base = 4 * i;
        oc[base]     = c0;
        oc[base + 1] = c1;
        oc[base + 2] = c2;
        oc[base + 3] = c3;

        // masked BCE: target is {0,1}; single-log form.
        float m0 = st[a10], m1 = st[a11], m2 = st[a12], m3 = st[a13];

        float q0 = fminf(fmaxf(p0, EPSV), 1.0f - EPSV);
        float q1 = fminf(fmaxf(p1, EPSV), 1.0f - EPSV);
        float q2 = fminf(fmaxf(p2, EPSV), 1.0f - EPSV);
        float q3 = fminf(fmaxf(p3, EPSV), 1.0f - EPSV);

        float k0 = (tv.x > 0.0f) ? 1.0f : m0;
        float k1 = (tv.y > 0.0f) ? 1.0f : m1;
        float k2 = (tv.z > 0.0f) ? 1.0f : m2;
        float k3 = (tv.w > 0.0f) ? 1.0f : m3;

        float g0 = (tv.x > 0.0f) ? q0 : 1.0f - q0;
        float g1 = (tv.y > 0.0f) ? q1 : 1.0f - q1;
        float g2 = (tv.z > 0.0f) ? q2 : 1.0f - q2;
        float g3 = (tv.w > 0.0f) ? q3 : 1.0f - q3;

        acc += k0 * __logf(g0);
        acc += k1 * __logf(g1);
        acc += k2 * __logf(g2);
        acc += k3 * __logf(g3);
    }

    // Block reduction (8 warps).
    #pragma unroll
    for (int o = 16; o > 0; o >>= 1)
        acc += __shfl_xor_sync(0xFFFFFFFFu, acc, o);
    __shared__ float red[8];
    if ((tid & 31) == 0) red[tid >> 5] = acc;
    __syncthreads();
    if (tid < 8) {
        float v = red[tid];
        #pragma unroll
        for (int o = 4; o > 0; o >>= 1)
            v += __shfl_xor_sync(0xFFu, v, o);
        if (tid == 0) g_partial[b] = v;
    }
}

__global__ void final_reduce_kernel(float* __restrict__ out, int nrows) {
    __shared__ double sred[32];
    int tid = threadIdx.x;
    double s = 0.0;
    for (int i = tid; i < nrows; i += 1024) s += (double)g_partial[i];
    #pragma unroll
    for (int o = 16; o > 0; o >>= 1)
        s += __shfl_xor_sync(0xFFFFFFFFu, s, o);
    if ((tid & 31) == 0) sred[tid >> 5] = s;
    __syncthreads();
    if (tid < 32) {
        double v = sred[tid];
        #pragma unroll
        for (int o = 16; o > 0; o >>= 1)
            v += __shfl_xor_sync(0xFFFFFFFFu, v, o);
        if (tid == 0) out[0] = (float)(-v / (double)nrows);
    }
}

extern "C" void kernel_launch(void* const* d_in, const int* in_sizes, int n_in,
                              void* d_out, int out_size) {
    const float* pred   = (const float*)d_in[0];
    const float* target = (const float*)d_in[1];
    const int*   parent = (const int*)d_in[2];
    // d_in[3] = level_of (implicit in ancestor chain), d_in[4] = mode (EVAL)

    const int N = in_sizes[2];                 // 8192
    const int B = in_sizes[0] / N;             // 4096

    float* out       = (float*)d_out;          // out[0] = loss
    float* out_clone = out + 1;                // out[1..] = pred_clone [B,N]

    anc_setup_kernel<<<(N + 255) / 256, 256>>>(parent, N);
    cond_sigmoid_row_kernel<<<B, 256>>>(pred, target, out_clone);
    final_reduce_kernel<<<1, 1024>>>(out, B);
}

// round 3
// speedup vs baseline: 1.3233x; 1.1686x over previous
#include <cuda_runtime.h>
#include <cuda_bf16.h>

#define NN 8192
#define BB 4096
#define EPSV 1e-7f
// Levels 0..2 = 8 + 128 + 2048 = 2184 internal nodes; every parent index < 2184.
#define ANC_SENT 2184
#define TBL 2192

__device__ unsigned short g_anc1[NN];        // parent, sentinel = ANC_SENT
__device__ ushort2        g_anc2[ANC_SENT];  // {a1, a2} for internal nodes
__device__ float          g_partial[BB];
__device__ int            g_done;            // zero-init; reset by last block

__global__ void anc_setup_kernel(const int* __restrict__ parent, int n) {
    int c = blockIdx.x * blockDim.x + threadIdx.x;
    if (c < n) {
        int a1 = parent[c];
        g_anc1[c] = (unsigned short)((a1 >= 0) ? a1 : ANC_SENT);
        if (c < ANC_SENT) {
            int a2 = (a1 >= 0) ? parent[a1] : -1;
            ushort2 v;
            v.x = (unsigned short)((a1 >= 0) ? a1 : ANC_SENT);
            v.y = (unsigned short)((a2 >= 0) ? a2 : ANC_SENT);
            g_anc2[c] = v;
        }
    }
}

__device__ __forceinline__ float fsigmoid(float x) {
    return __fdividef(1.0f, 1.0f + __expf(-x));
}

// One CTA per row.
// smem: sp[j]=sigmoid (internal nodes), sf[j]={cumprod, target} gather table.
__global__ __launch_bounds__(256, 6)
void cond_sigmoid_kernel(const float* __restrict__ pred,
                         const float* __restrict__ target,
                         float* __restrict__ out) {
    __shared__ float  sp[TBL];
    __shared__ float2 sf[TBL];
    __shared__ float  red[8];
    __shared__ double dred[8];
    __shared__ int    is_last;

    const int b   = blockIdx.x;
    const int tid = threadIdx.x;
    const size_t row = (size_t)b * NN;
    const float4* pr = (const float4*)(pred   + row);
    const float4* tg = (const float4*)(target + row);
    float* oc = out + 1 + row;   // pred_clone row (misaligned by 1 float)

    // Phase 1a: sigmoid + target for internal nodes [0, 2184).
    for (int i = tid; i < ANC_SENT / 4; i += 256) {
        float4 v = pr[i];
        float4 t = tg[i];
        float4 s;
        s.x = fsigmoid(v.x); s.y = fsigmoid(v.y);
        s.z = fsigmoid(v.z); s.w = fsigmoid(v.w);
        ((float4*)sp)[i] = s;
        int j = 4 * i;
        sf[j]     = make_float2(s.x, t.x);
        sf[j + 1] = make_float2(s.y, t.y);
        sf[j + 2] = make_float2(s.z, t.z);
        sf[j + 3] = make_float2(s.w, t.w);
    }
    if (tid == 0) { sp[ANC_SENT] = 1.0f; sf[ANC_SENT] = make_float2(1.0f, 1.0f); }
    __syncthreads();

    float acc = 0.0f;

    // Phase 1b: cumulative chain products for internal nodes, their outputs + loss.
    for (int j = tid; j < ANC_SENT; j += 256) {
        ushort2 a = g_anc2[j];
        float p  = sp[j];
        float cp = p * sp[a.x] * sp[a.y];
        sf[j].x  = cp;                 // 32-bit write; .y untouched (read elsewhere)
        oc[j]    = cp;                 // pred_clone for internal node
        float t = sf[j].y;
        float m = sf[a.x].y;           // sentinel row gives 1.0 for roots
        float q = fminf(fmaxf(p, EPSV), 1.0f - EPSV);
        float coef = (t > 0.0f) ? 1.0f : m;
        float arg  = (t > 0.0f) ? q    : 1.0f - q;
        acc += coef * __logf(arg);
    }
    __syncthreads();

    // Phase 2: stream leaf-level elements [2184, 8192). One LDS.64 gather each.
    const uint2* anc1v = (const uint2*)g_anc1;   // 4 ushorts per uint2
    #pragma unroll 2
    for (int i = ANC_SENT / 4 + tid; i < NN / 4; i += 256) {
        float4 pv = pr[i];
        float4 tv = tg[i];
        uint2 aw = anc1v[i];
        int a0 = aw.x & 0xFFFF, a1i = aw.x >> 16;
        int a2i = aw.y & 0xFFFF, a3i = aw.y >> 16;

        float2 f0 = sf[a0], f1 = sf[a1i], f2 = sf[a2i], f3 = sf[a3i];

        float p0 = fsigmoid(pv.x), p1 = fsigmoid(pv.y);
        float p2 = fsigmoid(pv.z), p3 = fsigmoid(pv.w);

        float c0 = p0 * f0.x, c1 = p1 * f1.x;
        float c2 = p2 * f2.x, c3 = p3 * f3.x;

        int base = 4 * i;
        oc[base] = c0;
        *(float2*)(oc + base + 1) = make_float2(c1, c2);   // 8B-aligned
        oc[base + 3] = c3;

        float q0 = fminf(fmaxf(p0, EPSV), 1.0f - EPSV);
        float q1 = fminf(fmaxf(p1, EPSV), 1.0f - EPSV);
        float q2 = fminf(fmaxf(p2, EPSV), 1.0f - EPSV);
        float q3 = fminf(fmaxf(p3, EPSV), 1.0f - EPSV);

        float k0 = (tv.x > 0.0f) ? 1.0f : f0.y;
        float k1 = (tv.y > 0.0f) ? 1.0f : f1.y;
        float k2 = (tv.z > 0.0f) ? 1.0f : f2.y;
        float k3 = (tv.w > 0.0f) ? 1.0f : f3.y;

        float g0 = (tv.x > 0.0f) ? q0 : 1.0f - q0;
        float g1 = (tv.y > 0.0f) ? q1 : 1.0f - q1;
        float g2 = (tv.z > 0.0f) ? q2 : 1.0f - q2;
        float g3 = (tv.w > 0.0f) ? q3 : 1.0f - q3;

        acc += k0 * __logf(g0);
        acc += k1 * __logf(g1);
        acc += k2 * __logf(g2);
        acc += k3 * __logf(g3);
    }

    // Block reduction.
    #pragma unroll
    for (int o = 16; o > 0; o >>= 1)
        acc += __shfl_xor_sync(0xFFFFFFFFu, acc, o);
    if ((tid & 31) == 0) red[tid >> 5] = acc;
    __syncthreads();
    if (tid == 0) {
        float v = red[0];
        #pragma unroll
        for (int w = 1; w < 8; w++) v += red[w];
        g_partial[b] = v;
        __threadfence();
        int prev = atomicAdd(&g_done, 1);
        is_last = (prev == (int)gridDim.x - 1);
    }
    __syncthreads();

    // Last block finalizes the mean (deterministic order).
    if (is_last) {
        __threadfence();
        double s = 0.0;
        for (int i = tid; i < BB; i += 256) s += (double)g_partial[i];
        #pragma unroll
        for (int o = 16; o > 0; o >>= 1)
            s += __shfl_xor_sync(0xFFFFFFFFu, s, o);
        if ((tid & 31) == 0) dred[tid >> 5] = s;
        __syncthreads();
        if (tid == 0) {
            double v = 0.0;
            #pragma unroll
            for (int w = 0; w < 8; w++) v += dred[w];
            out[0] = (float)(-v / (double)BB);
            g_done = 0;   // reset for next replay
        }
    }
}

extern "C" void kernel_launch(void* const* d_in, const int* in_sizes, int n_in,
                              void* d_out, int out_size) {
    const float* pred   = (const float*)d_in[0];
    const float* target = (const float*)d_in[1];
    const int*   parent = (const int*)d_in[2];
    // d_in[3] = level_of (implicit), d_in[4] = mode (EVAL)

    const int N = in_sizes[2];     // 8192
    const int B = in_sizes[0] / N; // 4096

    float* out = (float*)d_out;

    anc_setup_kernel<<<(N + 255) / 256, 256>>>(parent, N);
    cond_sigmoid_kernel<<<B, 256>>>(pred, target, out);
}

// round 4
// speedup vs baseline: 1.4213x; 1.0740x over previous
#include <cuda_runtime.h>
#include <cuda_bf16.h>

#define NN 8192
#define BB 4096
#define EPSV 1e-7f
// Levels: 0:[0,8) 1:[8,136) 2:[136,2184) 3:[2184,8192). All parents < 2184.
#define ANC_SENT 2184
#define TBL 2192

__device__ unsigned short g_anc1[NN];        // parent, sentinel = ANC_SENT
__device__ ushort2        g_anc2[ANC_SENT];  // {a1, a2} for internal nodes
__device__ float          g_partial[BB];
__device__ int            g_done;

__global__ void anc_setup_kernel(const int* __restrict__ parent, int n) {
    int c = blockIdx.x * blockDim.x + threadIdx.x;
    if (c < n) {
        int a1 = parent[c];
        g_anc1[c] = (unsigned short)((a1 >= 0) ? a1 : ANC_SENT);
        if (c < ANC_SENT) {
            int a2 = (a1 >= 0) ? parent[a1] : -1;
            ushort2 v;
            v.x = (unsigned short)((a1 >= 0) ? a1 : ANC_SENT);
            v.y = (unsigned short)((a2 >= 0) ? a2 : ANC_SENT);
            g_anc2[c] = v;
        }
    }
}

__device__ __forceinline__ float fsigmoid(float x) {
    return __fdividef(1.0f, 1.0f + __expf(-x));
}

// Sign-packed tables: value = (target ? -v : +v); v > 0 always.
// Sentinel = -1.0f  (|.| = 1 for chain product, sign => mask 1 for roots).
__global__ __launch_bounds__(256, 6)
void cond_sigmoid_kernel(const float* __restrict__ pred,
                         const float* __restrict__ target,
                         float* __restrict__ out) {
    __shared__ float sp[TBL];    // packed sigmoid (internal nodes)
    __shared__ float scf[TBL];   // packed cumulative product
    __shared__ float red[8];
    __shared__ double dred[8];
    __shared__ int    is_last;

    const int b   = blockIdx.x;
    const int tid = threadIdx.x;
    const size_t row = (size_t)b * NN;
    const float4* pr = (const float4*)(pred   + row);
    const float4* tg = (const float4*)(target + row);
    float* oc = out + 1 + row;

    // Phase 1a: packed sigmoid table for internal nodes [0, 2184).
    for (int i = tid; i < ANC_SENT / 4; i += 256) {
        float4 v = pr[i];
        float4 t = tg[i];
        float4 s;
        s.x = fsigmoid(v.x); s.y = fsigmoid(v.y);
        s.z = fsigmoid(v.z); s.w = fsigmoid(v.w);
        s.x = (t.x > 0.0f) ? -s.x : s.x;
        s.y = (t.y > 0.0f) ? -s.y : s.y;
        s.z = (t.z > 0.0f) ? -s.z : s.z;
        s.w = (t.w > 0.0f) ? -s.w : s.w;
        ((float4*)sp)[i] = s;
    }
    if (tid == 0) { sp[ANC_SENT] = -1.0f; scf[ANC_SENT] = -1.0f; }
    __syncthreads();

    float acc = 0.0f;

    // Phase 1b: cumulative chain products + internal-node outputs and loss.
    for (int j = tid; j < ANC_SENT; j += 256) {
        ushort2 a = g_anc2[j];
        float sj = sp[j];
        float s1 = sp[a.x];
        float s2 = sp[a.y];
        float p  = fabsf(sj);
        float cp = p * fabsf(s1) * fabsf(s2);
        scf[j] = (sj < 0.0f) ? -cp : cp;
        oc[j]  = cp;

        float m    = (s1 < 0.0f) ? 1.0f : 0.0f;   // target[parent]
        float q    = fminf(fmaxf(p, EPSV), 1.0f - EPSV);
        float coef = (sj < 0.0f) ? 1.0f : m;      // own target from sign
        float arg  = (sj < 0.0f) ? q    : 1.0f - q;
        acc += coef * __logf(arg);
    }
    __syncthreads();

    // Phase 2: stream leaves [2184, 8192). One LDS.32 gather per element.
    const uint2* anc1v = (const uint2*)g_anc1;
    #pragma unroll 2
    for (int i = ANC_SENT / 4 + tid; i < NN / 4; i += 256) {
        float4 pv = pr[i];
        float4 tv = tg[i];
        uint2 aw = anc1v[i];
        int a0 = aw.x & 0xFFFF, a1i = aw.x >> 16;
        int a2i = aw.y & 0xFFFF, a3i = aw.y >> 16;

        float s0 = scf[a0], s1 = scf[a1i], s2 = scf[a2i], s3 = scf[a3i];

        float p0 = fsigmoid(pv.x), p1 = fsigmoid(pv.y);
        float p2 = fsigmoid(pv.z), p3 = fsigmoid(pv.w);

        float c0 = p0 * fabsf(s0), c1 = p1 * fabsf(s1);
        float c2 = p2 * fabsf(s2), c3 = p3 * fabsf(s3);

        int base = 4 * i;
        oc[base] = c0;
        *(float2*)(oc + base + 1) = make_float2(c1, c2);
        oc[base + 3] = c3;

        float q0 = fminf(fmaxf(p0, EPSV), 1.0f - EPSV);
        float q1 = fminf(fmaxf(p1, EPSV), 1.0f - EPSV);
        float q2 = fminf(fmaxf(p2, EPSV), 1.0f - EPSV);
        float q3 = fminf(fmaxf(p3, EPSV), 1.0f - EPSV);

        float m0 = (s0 < 0.0f) ? 1.0f : 0.0f;
        float m1 = (s1 < 0.0f) ? 1.0f : 0.0f;
        float m2 = (s2 < 0.0f) ? 1.0f : 0.0f;
        float m3 = (s3 < 0.0f) ? 1.0f : 0.0f;

        float k0 = (tv.x > 0.0f) ? 1.0f : m0;
        float k1 = (tv.y > 0.0f) ? 1.0f : m1;
        float k2 = (tv.z > 0.0f) ? 1.0f : m2;
        float k3 = (tv.w > 0.0f) ? 1.0f : m3;

        float g0 = (tv.x > 0.0f) ? q0 : 1.0f - q0;
        float g1 = (tv.y > 0.0f) ? q1 : 1.0f - q1;
        float g2 = (tv.z > 0.0f) ? q2 : 1.0f - q2;
        float g3 = (tv.w > 0.0f) ? q3 : 1.0f - q3;

        acc += k0 * __logf(g0);
        acc += k1 * __logf(g1);
        acc += k2 * __logf(g2);
        acc += k3 * __logf(g3);
    }

    // Block reduction.
    #pragma unroll
    for (int o = 16; o > 0; o >>= 1)
        acc += __shfl_xor_sync(0xFFFFFFFFu, acc, o);
    if ((tid & 31) == 0) red[tid >> 5] = acc;
    __syncthreads();
    if (tid == 0) {
        float v = red[0];
        #pragma unroll
        for (int w = 1; w < 8; w++) v += red[w];
        g_partial[b] = v;
        __threadfence();
        int prev = atomicAdd(&g_done, 1);
        is_last = (prev == (int)gridDim.x - 1);
    }
    __syncthreads();

    if (is_last) {
        __threadfence();
        double s = 0.0;
        for (int i = tid; i < BB; i += 256) s += (double)g_partial[i];
        #pragma unroll
        for (int o = 16; o > 0; o >>= 1)
            s += __shfl_xor_sync(0xFFFFFFFFu, s, o);
        if ((tid & 31) == 0) dred[tid >> 5] = s;
        __syncthreads();
        if (tid == 0) {
            double v = 0.0;
            #pragma unroll
            for (int w = 0; w < 8; w++) v += dred[w];
            out[0] = (float)(-v / (double)BB);
            g_done = 0;
        }
    }
}

extern "C" void kernel_launch(void* const* d_in, const int* in_sizes, int n_in,
                              void* d_out, int out_size) {
    const float* pred   = (const float*)d_in[0];
    const float* target = (const float*)d_in[1];
    const int*   parent = (const int*)d_in[2];

    const int N = in_sizes[2];     // 8192
    const int B = in_sizes[0] / N; // 4096

    float* out = (float*)d_out;

    anc_setup_kernel<<<(N + 255) / 256, 256>>>(parent, N);
    cond_sigmoid_kernel<<<B, 256>>>(pred, target, out);
}